// round 14
// baseline (speedup 1.0000x reference)
#include <cuda_runtime.h>
#include <cuda_fp16.h>
#include <cstdint>

// ===================== problem constants =====================
#define N_TYPES   8
#define K_DIM     512
#define N_DIM     512
#define M_TILE    128
#define N_TILE    128
#define K_CHUNK   32
#define N_CHUNKS  (K_DIM / K_CHUNK)   // 16
#define THREADS   256

// A smem: 2 stages, 128 rows x 32 halves, pitch 40 halves (80B)
#define A_PITCH   40
#define A_STAGE_H (M_TILE * A_PITCH)          // 5120 halves / stage
// B smem: 3 stages, 32 rows x 128 halves, pitch 136 halves (272B)
#define B_PITCH   136
#define B_STAGE_H (K_CHUNK * B_PITCH)         // 4352 halves / stage
#define B_STAGES  3

#define SMEM_A_BYTES (2 * A_STAGE_H * 2)                // 20480
#define SMEM_B_BYTES (B_STAGES * B_STAGE_H * 2)         // 26112
#define SMEM_TOTAL   (SMEM_A_BYTES + SMEM_B_BYTES + N_TILE * 4)  // 47104

// fp16 weight image: [type][k][n], same linear layout as input weight
__device__ __half g_Wh[N_TYPES * K_DIM * N_DIM];   // 4 MB

// ===================== PTX helpers =====================
static __device__ __forceinline__ uint32_t smem_u32(const void* p) {
    return (uint32_t)__cvta_generic_to_shared(p);
}

static __device__ __forceinline__ void ldsm_x4(uint32_t* r, uint32_t addr) {
    asm volatile("ldmatrix.sync.aligned.m8n8.x4.shared.b16 {%0,%1,%2,%3}, [%4];"
                 : "=r"(r[0]), "=r"(r[1]), "=r"(r[2]), "=r"(r[3]) : "r"(addr) : "memory");
}

static __device__ __forceinline__ void ldsm_x4_t(uint32_t* r, uint32_t addr) {
    asm volatile("ldmatrix.sync.aligned.m8n8.x4.trans.shared.b16 {%0,%1,%2,%3}, [%4];"
                 : "=r"(r[0]), "=r"(r[1]), "=r"(r[2]), "=r"(r[3]) : "r"(addr) : "memory");
}

static __device__ __forceinline__ void mma_16816(float c[4], const uint32_t a[4],
                                                 uint32_t b0, uint32_t b1) {
    asm volatile(
        "mma.sync.aligned.m16n8k16.row.col.f32.f16.f16.f32 "
        "{%0,%1,%2,%3}, {%4,%5,%6,%7}, {%8,%9}, {%0,%1,%2,%3};"
        : "+f"(c[0]), "+f"(c[1]), "+f"(c[2]), "+f"(c[3])
        : "r"(a[0]), "r"(a[1]), "r"(a[2]), "r"(a[3]), "r"(b0), "r"(b1));
}

static __device__ __forceinline__ void cp_async16(uint32_t dst, const void* src) {
    asm volatile("cp.async.cg.shared.global [%0], [%1], 16;"
                 :: "r"(dst), "l"(src) : "memory");
}

#define CP_COMMIT() asm volatile("cp.async.commit_group;" ::: "memory")
#define CP_WAIT(n)  asm volatile("cp.async.wait_group %0;" :: "n"(n) : "memory")

// ===================== prepass: weight f32 -> f16 image =====================
__global__ void hetero_prep_w(const float* __restrict__ w) {
    int i = (blockIdx.x * blockDim.x + threadIdx.x) * 4;   // exact grid
    float4 v = *(const float4*)(w + i);
    __half2 h0 = __float22half2_rn(make_float2(v.x, v.y));
    __half2 h1 = __float22half2_rn(make_float2(v.z, v.w));
    *(uint2*)&g_Wh[i] = make_uint2(*(uint32_t*)&h0, *(uint32_t*)&h1);
}

// pack 8 floats into one uint4 of fp16
static __device__ __forceinline__ uint4 pack8(float4 v0, float4 v1) {
    __half2 h0 = __float22half2_rn(make_float2(v0.x, v0.y));
    __half2 h1 = __float22half2_rn(make_float2(v0.z, v0.w));
    __half2 h2 = __float22half2_rn(make_float2(v1.x, v1.y));
    __half2 h3 = __float22half2_rn(make_float2(v1.z, v1.w));
    return make_uint4(*(uint32_t*)&h0, *(uint32_t*)&h1,
                      *(uint32_t*)&h2, *(uint32_t*)&h3);
}

// ===================== main GEMM kernel =====================
__global__ void __launch_bounds__(THREADS, 2)
hetero_gemm_kernel(const float* __restrict__ x,
                   const int* __restrict__ tv,
                   const float* __restrict__ bias,
                   float* __restrict__ out) {
    extern __shared__ __align__(16) char smem[];
    __half* sA    = (__half*)smem;                              // 2 stages
    __half* sB    = (__half*)(smem + SMEM_A_BYTES);             // 3-stage ring
    float*  sBias = (float*)(smem + SMEM_A_BYTES + SMEM_B_BYTES);

    const int tid  = threadIdx.x;
    const int lane = tid & 31;
    const int warp = tid >> 5;
    const int wm   = warp >> 1;         // 0..3  (M, 32 rows each)
    const int wn   = warp & 1;          // 0..1  (N, 64 cols each)

    const int bx = blockIdx.x;
    const int m0 = (bx >> 2) * M_TILE;
    const int n0 = (bx & 3)  * N_TILE;

    const int t_first = tv[m0];
    const int t_last  = tv[m0 + M_TILE - 1];
    const bool multi  = (t_first != t_last);

    // ---- A staging geometry: 2 threads/row, 16 floats each ----
    const int arow = tid >> 1;                    // 0..127
    const int aseg = (tid & 1) * 16;              // half offset within 32-chunk
    const int rt_row = tv[m0 + arow];

    // ---- B staging geometry: 8 threads/row, 16 halves (2 x 16B) each ----
    const int b_row = tid >> 3;                   // 0..31
    const int b_col = (tid & 7) * 16;             // halves within 128-col row

    const uint32_t sAu = smem_u32(sA);
    const uint32_t sBu = smem_u32(sB);

    const int l16 = lane & 15;
    const int lh8 = (lane >> 4) * 8;

    float acc[2][8][4];                 // [mi 16-row][nb 8-col][frag]
    #pragma unroll
    for (int i = 0; i < 2; ++i)
        #pragma unroll
        for (int j = 0; j < 8; ++j)
            #pragma unroll
            for (int q = 0; q < 4; ++q) acc[i][j][q] = 0.f;

    for (int t = t_first; t <= t_last; ++t) {
        const __half* wsrc = g_Wh + (size_t)t * (K_DIM * N_DIM);
        const bool amask = !multi || (rt_row == t);
        const float* xrow = x + (size_t)(m0 + arow) * K_DIM + aseg;

        if (t != t_first) __syncthreads();   // rings fully read before restage

        float4 av0, av1, av2, av3;

        // ---------- prologue: issue B(0),B(1); stage A(0) ----------
        {
            #pragma unroll
            for (int s = 0; s < 2; ++s) {
                const __half* bsrc = wsrc + (size_t)(s * K_CHUNK + b_row) * N_DIM + n0 + b_col;
                uint32_t bdst = sBu + (uint32_t)(s * B_STAGE_H + b_row * B_PITCH + b_col) * 2u;
                cp_async16(bdst,      bsrc);
                cp_async16(bdst + 16, bsrc + 8);
                CP_COMMIT();
            }
            uint4 u0 = make_uint4(0, 0, 0, 0), u1 = u0;
            if (amask) {
                av0 = *(const float4*)(xrow);
                av1 = *(const float4*)(xrow + 4);
                av2 = *(const float4*)(xrow + 8);
                av3 = *(const float4*)(xrow + 12);
                u0 = pack8(av0, av1);
                u1 = pack8(av2, av3);
            }
            *(uint4*)&sA[arow * A_PITCH + aseg]     = u0;
            *(uint4*)&sA[arow * A_PITCH + aseg + 8] = u1;
            CP_WAIT(1);          // B(0) landed
            __syncthreads();
        }

        int bcur = 0;            // ring stage holding B(kc)
        int biss = 2;            // ring stage to receive B(kc+2)

        // ---------- main loop over K chunks ----------
        #pragma unroll 1
        for (int kc = 0; kc < N_CHUNKS; ++kc) {
            const int anxt = (kc + 1) & 1;

            if (kc + 2 < N_CHUNKS) {
                // issue B(kc+2) into ring stage biss
                const __half* bsrc = wsrc + (size_t)((kc + 2) * K_CHUNK + b_row) * N_DIM
                                   + n0 + b_col;
                uint32_t bdst = sBu + (uint32_t)(biss * B_STAGE_H + b_row * B_PITCH + b_col) * 2u;
                cp_async16(bdst,      bsrc);
                cp_async16(bdst + 16, bsrc + 8);
                CP_COMMIT();
            }
            if (kc + 1 < N_CHUNKS && amask) {
                // prefetch A(kc+1) into regs
                const float* p = xrow + (kc + 1) * K_CHUNK;
                av0 = *(const float4*)(p);
                av1 = *(const float4*)(p + 4);
                av2 = *(const float4*)(p + 8);
                av3 = *(const float4*)(p + 12);
            }

            // ---- MMA on A stage kc&1, B ring stage bcur: 2 x k16 steps ----
            const uint32_t abase = sAu + (uint32_t)((kc & 1) * A_STAGE_H) * 2u;
            const uint32_t bbase = sBu + (uint32_t)(bcur * B_STAGE_H) * 2u;
            #pragma unroll
            for (int ks = 0; ks < 2; ++ks) {
                uint32_t a0[4], a1[4];
                uint32_t aaddr = abase
                    + (uint32_t)((wm * 32 + l16) * A_PITCH + ks * 16 + lh8) * 2u;
                ldsm_x4(a0, aaddr);
                ldsm_x4(a1, aaddr + (uint32_t)(16 * A_PITCH) * 2u);
                #pragma unroll
                for (int nb4 = 0; nb4 < 4; ++nb4) {
                    uint32_t b[4];
                    uint32_t baddr = bbase
                        + (uint32_t)((ks * 16 + l16) * B_PITCH + wn * 64 + nb4 * 16 + lh8) * 2u;
                    ldsm_x4_t(b, baddr);
                    mma_16816(acc[0][2 * nb4],     a0, b[0], b[1]);
                    mma_16816(acc[0][2 * nb4 + 1], a0, b[2], b[3]);
                    mma_16816(acc[1][2 * nb4],     a1, b[0], b[1]);
                    mma_16816(acc[1][2 * nb4 + 1], a1, b[2], b[3]);
                }
            }

            if (kc + 1 < N_CHUNKS) {
                // convert + STS A(kc+1)
                uint4 u0 = make_uint4(0, 0, 0, 0), u1 = u0;
                if (amask) {
                    u0 = pack8(av0, av1);
                    u1 = pack8(av2, av3);
                }
                *(uint4*)&sA[anxt * A_STAGE_H + arow * A_PITCH + aseg]     = u0;
                *(uint4*)&sA[anxt * A_STAGE_H + arow * A_PITCH + aseg + 8] = u1;

                if (kc + 2 < N_CHUNKS) CP_WAIT(1);   // B(kc+1) landed, B(kc+2) in flight
                else                   CP_WAIT(0);   // drain tail
                __syncthreads();
            }

            if (++bcur == B_STAGES) bcur = 0;
            if (++biss == B_STAGES) biss = 0;
        }
    }

    // ---------- epilogue ----------
    __syncthreads();
    if (!multi && tid < N_TILE) {
        sBias[tid] = bias[(size_t)t_first * N_DIM + n0 + tid];
    }
    __syncthreads();

    const int lrow = lane >> 2;
    const int lcol = (lane & 3) * 2;
    #pragma unroll
    for (int mi = 0; mi < 2; ++mi) {
        #pragma unroll
        for (int rr = 0; rr < 2; ++rr) {
            const int rowg = m0 + wm * 32 + mi * 16 + rr * 8 + lrow;
            const float* brow = bias + (size_t)tv[rowg] * N_DIM + n0;  // used if multi
            float* op = out + (size_t)rowg * N_DIM + n0;
            #pragma unroll
            for (int nb = 0; nb < 8; ++nb) {
                const int c = wn * 64 + nb * 8 + lcol;   // col within N-tile
                float b0, b1;
                if (multi) { b0 = brow[c]; b1 = brow[c + 1]; }
                else       { b0 = sBias[c]; b1 = sBias[c + 1]; }
                float2 o;
                o.x = acc[mi][nb][rr * 2 + 0] + b0;
                o.y = acc[mi][nb][rr * 2 + 1] + b1;
                *(float2*)(op + c) = o;
            }
        }
    }
}

// ===================== launch =====================
// Inputs bound BY ELEMENT COUNT (pairwise distinct):
//   x: 67108864 f32, weight: 2097152 f32, type_vec: 131072 int32, bias: 4096 f32
extern "C" void kernel_launch(void* const* d_in, const int* in_sizes, int n_in,
                              void* d_out, int out_size) {
    const float* x    = nullptr;
    const int*   tv   = nullptr;
    const float* w    = nullptr;
    const float* bias = nullptr;

    int x_elems = 0;
    for (int i = 0; i < n_in; ++i) {
        const int sz = in_sizes[i];
        if (sz == N_TYPES * K_DIM * N_DIM) {
            w = (const float*)d_in[i];
        } else if (sz == N_TYPES * N_DIM) {
            bias = (const float*)d_in[i];
        } else if (sz >= 2 * N_TYPES * K_DIM * N_DIM) {
            x = (const float*)d_in[i];
            x_elems = sz;
        } else {
            tv = (const int*)d_in[i];
        }
    }

    const int nrows = x_elems / K_DIM;                        // 131072
    const int grid  = (nrows / M_TILE) * (N_DIM / N_TILE);    // 4096

    cudaFuncSetAttribute(hetero_gemm_kernel,
                         cudaFuncAttributeMaxDynamicSharedMemorySize, SMEM_TOTAL);

    hetero_prep_w<<<(N_TYPES * K_DIM * N_DIM) / (256 * 4), 256>>>(w);
    hetero_gemm_kernel<<<grid, THREADS, SMEM_TOTAL>>>(x, tv, bias, (float*)d_out);
}

// round 15
// speedup vs baseline: 1.0184x; 1.0184x over previous
#include <cuda_runtime.h>
#include <cuda_fp16.h>
#include <cstdint>

// ===================== problem constants =====================
#define N_TYPES   8
#define K_DIM     512
#define N_DIM     512
#define M_TILE    64
#define N_TILE    256
#define K_CHUNK   32
#define N_CHUNKS  (K_DIM / K_CHUNK)   // 16
#define THREADS   256

// A smem: 2 stages, 64 rows x 32 halves, pitch 40 halves (80B)
#define A_PITCH   40
#define A_STAGE_H (M_TILE * A_PITCH)          // 2560 halves / stage
// B smem: 2 stages, 32 rows x 256 halves, pitch 264 halves (528B)
#define B_PITCH   264
#define B_STAGE_H (K_CHUNK * B_PITCH)         // 8448 halves / stage

#define SMEM_A_BYTES (2 * A_STAGE_H * 2)                // 10240
#define SMEM_B_BYTES (2 * B_STAGE_H * 2)                // 33792
#define SMEM_TOTAL   (SMEM_A_BYTES + SMEM_B_BYTES + N_TILE * 4)  // 45056

// fp16 weight image: [type][k][n], same linear layout as input weight
__device__ __half g_Wh[N_TYPES * K_DIM * N_DIM];   // 4 MB

// ===================== PTX helpers =====================
static __device__ __forceinline__ uint32_t smem_u32(const void* p) {
    return (uint32_t)__cvta_generic_to_shared(p);
}

static __device__ __forceinline__ void ldsm_x4(uint32_t* r, uint32_t addr) {
    asm volatile("ldmatrix.sync.aligned.m8n8.x4.shared.b16 {%0,%1,%2,%3}, [%4];"
                 : "=r"(r[0]), "=r"(r[1]), "=r"(r[2]), "=r"(r[3]) : "r"(addr) : "memory");
}

static __device__ __forceinline__ void ldsm_x4_t(uint32_t* r, uint32_t addr) {
    asm volatile("ldmatrix.sync.aligned.m8n8.x4.trans.shared.b16 {%0,%1,%2,%3}, [%4];"
                 : "=r"(r[0]), "=r"(r[1]), "=r"(r[2]), "=r"(r[3]) : "r"(addr) : "memory");
}

static __device__ __forceinline__ void mma_16816(float c[4], const uint32_t a[4],
                                                 uint32_t b0, uint32_t b1) {
    asm volatile(
        "mma.sync.aligned.m16n8k16.row.col.f32.f16.f16.f32 "
        "{%0,%1,%2,%3}, {%4,%5,%6,%7}, {%8,%9}, {%0,%1,%2,%3};"
        : "+f"(c[0]), "+f"(c[1]), "+f"(c[2]), "+f"(c[3])
        : "r"(a[0]), "r"(a[1]), "r"(a[2]), "r"(a[3]), "r"(b0), "r"(b1));
}

static __device__ __forceinline__ void cp_async16(uint32_t dst, const void* src) {
    asm volatile("cp.async.cg.shared.global [%0], [%1], 16;"
                 :: "r"(dst), "l"(src) : "memory");
}

#define CP_COMMIT() asm volatile("cp.async.commit_group;" ::: "memory")
#define CP_WAIT(n)  asm volatile("cp.async.wait_group %0;" :: "n"(n) : "memory")

// ===================== prepass: weight f32 -> f16 image =====================
__global__ void hetero_prep_w(const float* __restrict__ w) {
    int i = (blockIdx.x * blockDim.x + threadIdx.x) * 4;   // exact grid
    float4 v = *(const float4*)(w + i);
    __half2 h0 = __float22half2_rn(make_float2(v.x, v.y));
    __half2 h1 = __float22half2_rn(make_float2(v.z, v.w));
    *(uint2*)&g_Wh[i] = make_uint2(*(uint32_t*)&h0, *(uint32_t*)&h1);
}

// pack 8 floats into one uint4 of fp16
static __device__ __forceinline__ uint4 pack8(float4 v0, float4 v1) {
    __half2 h0 = __float22half2_rn(make_float2(v0.x, v0.y));
    __half2 h1 = __float22half2_rn(make_float2(v0.z, v0.w));
    __half2 h2 = __float22half2_rn(make_float2(v1.x, v1.y));
    __half2 h3 = __float22half2_rn(make_float2(v1.z, v1.w));
    return make_uint4(*(uint32_t*)&h0, *(uint32_t*)&h1,
                      *(uint32_t*)&h2, *(uint32_t*)&h3);
}

// ===================== main GEMM kernel =====================
__global__ void __launch_bounds__(THREADS, 2)
hetero_gemm_kernel(const float* __restrict__ x,
                   const int* __restrict__ tv,
                   const float* __restrict__ bias,
                   float* __restrict__ out) {
    extern __shared__ __align__(16) char smem[];
    __half* sA    = (__half*)smem;                              // 2 stages
    __half* sB    = (__half*)(smem + SMEM_A_BYTES);             // 2 stages
    float*  sBias = (float*)(smem + SMEM_A_BYTES + SMEM_B_BYTES);

    const int tid  = threadIdx.x;
    const int lane = tid & 31;
    const int warp = tid >> 5;
    const int wm   = warp >> 2;         // 0..1  (M, 32 rows each)
    const int wn   = warp & 3;          // 0..3  (N, 64 cols each)

    const int bx = blockIdx.x;
    const int m0 = (bx >> 1) * M_TILE;
    const int n0 = (bx & 1)  * N_TILE;

    const int t_first = tv[m0];
    const int t_last  = tv[m0 + M_TILE - 1];
    const bool multi  = (t_first != t_last);

    // ---- A staging geometry: 4 threads/row, 8 floats each ----
    const int arow = tid >> 2;                    // 0..63
    const int aseg = (tid & 3) * 8;               // float offset within 32-chunk
    const int rt_row = tv[m0 + arow];

    // ---- B staging geometry: 8 threads/row, 32 halves (4 x 16B) each ----
    const int b_row = tid >> 3;                   // 0..31
    const int b_col = (tid & 7) * 32;             // halves within 256-col row

    const uint32_t sAu = smem_u32(sA);
    const uint32_t sBu = smem_u32(sB);

    const int l16 = lane & 15;
    const int lh8 = (lane >> 4) * 8;

    float acc[2][8][4];                 // [mi 16-row][nb 8-col][frag]
    #pragma unroll
    for (int i = 0; i < 2; ++i)
        #pragma unroll
        for (int j = 0; j < 8; ++j)
            #pragma unroll
            for (int q = 0; q < 4; ++q) acc[i][j][q] = 0.f;

    for (int t = t_first; t <= t_last; ++t) {
        const __half* wsrc = g_Wh + (size_t)t * (K_DIM * N_DIM);
        const bool amask = !multi || (rt_row == t);
        const float* xrow = x + (size_t)(m0 + arow) * K_DIM + aseg;

        if (t != t_first) __syncthreads();   // buffers fully read before restage

        float4 av0, av1;

        // ---------- prologue: issue B(0); stage A(0) ----------
        {
            const __half* bsrc = wsrc + (size_t)b_row * N_DIM + n0 + b_col;
            uint32_t bdst = sBu + (uint32_t)(b_row * B_PITCH + b_col) * 2u;
            #pragma unroll
            for (int j = 0; j < 4; ++j)
                cp_async16(bdst + 16u * j, bsrc + 8 * j);
            CP_COMMIT();

            uint4 u = make_uint4(0, 0, 0, 0);
            if (amask) {
                av0 = *(const float4*)(xrow);
                av1 = *(const float4*)(xrow + 4);
                u = pack8(av0, av1);
            }
            *(uint4*)&sA[arow * A_PITCH + aseg] = u;
            CP_WAIT(0);
            __syncthreads();
        }

        // ---------- main loop over K chunks ----------
        #pragma unroll 1
        for (int kc = 0; kc < N_CHUNKS; ++kc) {
            const int cur = kc & 1;
            const int nxt = cur ^ 1;

            if (kc + 1 < N_CHUNKS) {
                // issue B(kc+1) into stage nxt
                const __half* bsrc = wsrc + (size_t)((kc + 1) * K_CHUNK + b_row) * N_DIM
                                   + n0 + b_col;
                uint32_t bdst = sBu + (uint32_t)(nxt * B_STAGE_H + b_row * B_PITCH + b_col) * 2u;
                #pragma unroll
                for (int j = 0; j < 4; ++j)
                    cp_async16(bdst + 16u * j, bsrc + 8 * j);
                CP_COMMIT();
                // prefetch A(kc+1) into regs
                if (amask) {
                    const float* p = xrow + (kc + 1) * K_CHUNK;
                    av0 = *(const float4*)(p);
                    av1 = *(const float4*)(p + 4);
                }
            }

            // ---- MMA on stage cur: 2 x k16 steps ----
            const uint32_t abase = sAu + (uint32_t)(cur * A_STAGE_H) * 2u;
            const uint32_t bbase = sBu + (uint32_t)(cur * B_STAGE_H) * 2u;
            #pragma unroll
            for (int ks = 0; ks < 2; ++ks) {
                uint32_t a0[4], a1[4];
                uint32_t aaddr = abase
                    + (uint32_t)((wm * 32 + l16) * A_PITCH + ks * 16 + lh8) * 2u;
                ldsm_x4(a0, aaddr);
                ldsm_x4(a1, aaddr + (uint32_t)(16 * A_PITCH) * 2u);
                #pragma unroll
                for (int nb4 = 0; nb4 < 4; ++nb4) {
                    uint32_t b[4];
                    uint32_t baddr = bbase
                        + (uint32_t)((ks * 16 + l16) * B_PITCH + wn * 64 + nb4 * 16 + lh8) * 2u;
                    ldsm_x4_t(b, baddr);
                    mma_16816(acc[0][2 * nb4],     a0, b[0], b[1]);
                    mma_16816(acc[0][2 * nb4 + 1], a0, b[2], b[3]);
                    mma_16816(acc[1][2 * nb4],     a1, b[0], b[1]);
                    mma_16816(acc[1][2 * nb4 + 1], a1, b[2], b[3]);
                }
            }

            if (kc + 1 < N_CHUNKS) {
                // convert + STS A(kc+1) into nxt
                uint4 u = make_uint4(0, 0, 0, 0);
                if (amask) u = pack8(av0, av1);
                *(uint4*)&sA[nxt * A_STAGE_H + arow * A_PITCH + aseg] = u;
                CP_WAIT(0);
                __syncthreads();
            }
        }
    }

    // ---------- epilogue ----------
    __syncthreads();
    if (!multi) {
        sBias[tid] = bias[(size_t)t_first * N_DIM + n0 + tid];
    }
    __syncthreads();

    const int lrow = lane >> 2;
    const int lcol = (lane & 3) * 2;
    #pragma unroll
    for (int mi = 0; mi < 2; ++mi) {
        #pragma unroll
        for (int rr = 0; rr < 2; ++rr) {
            const int rowg = m0 + wm * 32 + mi * 16 + rr * 8 + lrow;
            const float* brow = bias + (size_t)tv[rowg] * N_DIM + n0;  // used if multi
            float* op = out + (size_t)rowg * N_DIM + n0;
            #pragma unroll
            for (int nb = 0; nb < 8; ++nb) {
                const int c = wn * 64 + nb * 8 + lcol;   // col within N-tile
                float b0, b1;
                if (multi) { b0 = brow[c]; b1 = brow[c + 1]; }
                else       { b0 = sBias[c]; b1 = sBias[c + 1]; }
                float2 o;
                o.x = acc[mi][nb][rr * 2 + 0] + b0;
                o.y = acc[mi][nb][rr * 2 + 1] + b1;
                *(float2*)(op + c) = o;
            }
        }
    }
}

// ===================== launch =====================
// Inputs bound BY ELEMENT COUNT (pairwise distinct):
//   x: 67108864 f32, weight: 2097152 f32, type_vec: 131072 int32, bias: 4096 f32
extern "C" void kernel_launch(void* const* d_in, const int* in_sizes, int n_in,
                              void* d_out, int out_size) {
    const float* x    = nullptr;
    const int*   tv   = nullptr;
    const float* w    = nullptr;
    const float* bias = nullptr;

    int x_elems = 0;
    for (int i = 0; i < n_in; ++i) {
        const int sz = in_sizes[i];
        if (sz == N_TYPES * K_DIM * N_DIM) {
            w = (const float*)d_in[i];
        } else if (sz == N_TYPES * N_DIM) {
            bias = (const float*)d_in[i];
        } else if (sz >= 2 * N_TYPES * K_DIM * N_DIM) {
            x = (const float*)d_in[i];
            x_elems = sz;
        } else {
            tv = (const int*)d_in[i];
        }
    }

    const int nrows = x_elems / K_DIM;                        // 131072
    const int grid  = (nrows / M_TILE) * (N_DIM / N_TILE);    // 4096

    cudaFuncSetAttribute(hetero_gemm_kernel,
                         cudaFuncAttributeMaxDynamicSharedMemorySize, SMEM_TOTAL);

    hetero_prep_w<<<(N_TYPES * K_DIM * N_DIM) / (256 * 4), 256>>>(w);
    hetero_gemm_kernel<<<grid, THREADS, SMEM_TOTAL>>>(x, tv, bias, (float*)d_out);
}

// round 16
// speedup vs baseline: 1.2468x; 1.2242x over previous
#include <cuda_runtime.h>
#include <cuda_fp16.h>
#include <cstdint>

// ===================== problem constants =====================
#define N_TYPES   8
#define K_DIM     512
#define N_DIM     512
#define M_TILE    128
#define N_TILE    256
#define K_CHUNK   32
#define N_CHUNKS  (K_DIM / K_CHUNK)   // 16
#define THREADS   512

// A smem: 128 rows x 32 halves, pitch 40 halves (80B) -> conflict-free ldmatrix
#define A_PITCH   40
#define A_BUF_H   (M_TILE * A_PITCH)          // 5120 halves / stage
// B smem: 32 rows x 256 halves, pitch 264 halves (528B)
#define B_PITCH   264
#define B_BUF_H   (K_CHUNK * B_PITCH)         // 8448 halves / stage

#define SMEM_A_BYTES (2 * A_BUF_H * 2)        // 20480
#define SMEM_B_BYTES (2 * B_BUF_H * 2)        // 33792
#define SMEM_TOTAL   (SMEM_A_BYTES + SMEM_B_BYTES + N_TILE * 4)  // 55296

// fp16 weight image: [type][k][n], same linear layout as input weight
__device__ __half g_Wh[N_TYPES * K_DIM * N_DIM];   // 4 MB

// ===================== PTX helpers =====================
static __device__ __forceinline__ uint32_t smem_u32(const void* p) {
    return (uint32_t)__cvta_generic_to_shared(p);
}

static __device__ __forceinline__ void ldsm_x4(uint32_t r[4], uint32_t addr) {
    asm volatile("ldmatrix.sync.aligned.m8n8.x4.shared.b16 {%0,%1,%2,%3}, [%4];"
                 : "=r"(r[0]), "=r"(r[1]), "=r"(r[2]), "=r"(r[3]) : "r"(addr) : "memory");
}

static __device__ __forceinline__ void ldsm_x4_t(uint32_t r[4], uint32_t addr) {
    asm volatile("ldmatrix.sync.aligned.m8n8.x4.trans.shared.b16 {%0,%1,%2,%3}, [%4];"
                 : "=r"(r[0]), "=r"(r[1]), "=r"(r[2]), "=r"(r[3]) : "r"(addr) : "memory");
}

static __device__ __forceinline__ void mma_16816(float c[4], const uint32_t a[4],
                                                 uint32_t b0, uint32_t b1) {
    asm volatile(
        "mma.sync.aligned.m16n8k16.row.col.f32.f16.f16.f32 "
        "{%0,%1,%2,%3}, {%4,%5,%6,%7}, {%8,%9}, {%0,%1,%2,%3};"
        : "+f"(c[0]), "+f"(c[1]), "+f"(c[2]), "+f"(c[3])
        : "r"(a[0]), "r"(a[1]), "r"(a[2]), "r"(a[3]), "r"(b0), "r"(b1));
}

static __device__ __forceinline__ void cp_async16(uint32_t dst, const void* src) {
    asm volatile("cp.async.cg.shared.global [%0], [%1], 16;"
                 :: "r"(dst), "l"(src) : "memory");
}

#define CP_COMMIT() asm volatile("cp.async.commit_group;" ::: "memory")
#define CP_WAIT0()  asm volatile("cp.async.wait_group 0;"  ::: "memory")

// ===================== prepass: weight f32 -> f16 image =====================
__global__ void hetero_prep_kernel(const float* __restrict__ w) {
    int i = (blockIdx.x * blockDim.x + threadIdx.x) * 4;   // exact grid
    float4 v = *(const float4*)(w + i);
    __half2 h0 = __float22half2_rn(make_float2(v.x, v.y));
    __half2 h1 = __float22half2_rn(make_float2(v.z, v.w));
    uint2 u;
    u.x = *(uint32_t*)&h0;
    u.y = *(uint32_t*)&h1;
    *(uint2*)&g_Wh[i] = u;
}

// ===================== main GEMM kernel =====================
__global__ void __launch_bounds__(THREADS, 1)
hetero_gemm_kernel(const float* __restrict__ x,
                   const int* __restrict__ tv,
                   const float* __restrict__ bias,
                   float* __restrict__ out) {
    extern __shared__ __align__(16) char smem[];
    __half* sA    = (__half*)smem;                              // 2 stages
    __half* sB    = (__half*)(smem + SMEM_A_BYTES);             // 2 stages
    float*  sBias = (float*)(smem + SMEM_A_BYTES + SMEM_B_BYTES);

    const int tid  = threadIdx.x;
    const int lane = tid & 31;
    const int warp = tid >> 5;
    const int wm   = warp >> 2;         // 0..3  (M, 32 rows each)
    const int wn   = warp & 3;          // 0..3  (N, 64 cols each)

    const int bx = blockIdx.x;
    const int m0 = (bx >> 1) * M_TILE;
    const int n0 = (bx & 1)  * N_TILE;

    const int t_first = tv[m0];
    const int t_last  = tv[m0 + M_TILE - 1];
    const bool multi  = (t_first != t_last);

    // ---- A staging geometry: 4 threads/row, 8 floats each ----
    const int arow = tid >> 2;                    // 0..127
    const int aseg = (tid & 3) * 8;               // k offset within 32-chunk
    const int rt_row = tv[m0 + arow];

    // ---- B staging geometry: 16 threads/row, 16 halves (2 x uint4) each ----
    const int b_row = tid >> 4;                   // 0..31
    const int b_col = (tid & 15) * 16;            // halves within 256-col row

    const uint32_t sAu = smem_u32(sA);
    const uint32_t sBu = smem_u32(sB);

    const int l16 = lane & 15;
    const int lh8 = (lane >> 4) * 8;

    float acc[2][8][4];                 // [mi 16-row][nb 8-col][frag]
    #pragma unroll
    for (int i = 0; i < 2; ++i)
        #pragma unroll
        for (int j = 0; j < 8; ++j)
            #pragma unroll
            for (int q = 0; q < 4; ++q) acc[i][j][q] = 0.f;

    for (int t = t_first; t <= t_last; ++t) {
        const __half* wsrc = g_Wh + (size_t)t * (K_DIM * N_DIM);
        const bool amask = !multi || (rt_row == t);
        const float* xrow = x + (size_t)(m0 + arow) * K_DIM + aseg;

        float4 av0, av1;

        // ---------- prologue: stage chunk 0 into stage 0 ----------
        {
            const __half* bsrc = wsrc + (size_t)b_row * N_DIM + n0 + b_col;
            uint32_t bdst = sBu + (uint32_t)(b_row * B_PITCH + b_col) * 2u;
            cp_async16(bdst,      bsrc);
            cp_async16(bdst + 16, bsrc + 8);
            CP_COMMIT();
            uint4 u = make_uint4(0, 0, 0, 0);
            if (amask) {
                av0 = *(const float4*)(xrow);
                av1 = *(const float4*)(xrow + 4);
                __half2 h0 = __float22half2_rn(make_float2(av0.x, av0.y));
                __half2 h1 = __float22half2_rn(make_float2(av0.z, av0.w));
                __half2 h2 = __float22half2_rn(make_float2(av1.x, av1.y));
                __half2 h3 = __float22half2_rn(make_float2(av1.z, av1.w));
                u = make_uint4(*(uint32_t*)&h0, *(uint32_t*)&h1,
                               *(uint32_t*)&h2, *(uint32_t*)&h3);
            }
            *(uint4*)&sA[arow * A_PITCH + aseg] = u;
            CP_WAIT0();
            __syncthreads();
        }

        // ---------- main loop over K chunks ----------
        for (int kc = 0; kc < N_CHUNKS; ++kc) {
            const int cur = kc & 1;
            const int nxt = cur ^ 1;

            if (kc + 1 < N_CHUNKS) {
                // stage B(kc+1) via cp.async into nxt
                const __half* bsrc = wsrc + (size_t)((kc + 1) * K_CHUNK + b_row) * N_DIM
                                   + n0 + b_col;
                uint32_t bdst = sBu + (uint32_t)(nxt * B_BUF_H + b_row * B_PITCH + b_col) * 2u;
                cp_async16(bdst,      bsrc);
                cp_async16(bdst + 16, bsrc + 8);
                CP_COMMIT();
                // prefetch A(kc+1) into regs
                if (amask) {
                    av0 = *(const float4*)(xrow + (kc + 1) * K_CHUNK);
                    av1 = *(const float4*)(xrow + (kc + 1) * K_CHUNK + 4);
                }
            }

            // ---- MMA on cur stage: 2 x k16 steps ----
            const uint32_t abase = sAu + (uint32_t)(cur * A_BUF_H) * 2u;
            const uint32_t bbase = sBu + (uint32_t)(cur * B_BUF_H) * 2u;
            #pragma unroll
            for (int ks = 0; ks < 2; ++ks) {
                uint32_t a0[4], a1[4];
                uint32_t aaddr = abase
                    + (uint32_t)((wm * 32 + l16) * A_PITCH + ks * 16 + lh8) * 2u;
                ldsm_x4(a0, aaddr);
                ldsm_x4(a1, aaddr + (uint32_t)(16 * A_PITCH) * 2u);
                #pragma unroll
                for (int nb4 = 0; nb4 < 4; ++nb4) {
                    uint32_t b[4];
                    uint32_t baddr = bbase
                        + (uint32_t)((ks * 16 + l16) * B_PITCH + wn * 64 + nb4 * 16 + lh8) * 2u;
                    ldsm_x4_t(b, baddr);
                    mma_16816(acc[0][2 * nb4],     a0, b[0], b[1]);
                    mma_16816(acc[0][2 * nb4 + 1], a0, b[2], b[3]);
                    mma_16816(acc[1][2 * nb4],     a1, b[0], b[1]);
                    mma_16816(acc[1][2 * nb4 + 1], a1, b[2], b[3]);
                }
            }

            if (kc + 1 < N_CHUNKS) {
                // convert + STS A(kc+1) into nxt
                uint4 u = make_uint4(0, 0, 0, 0);
                if (amask) {
                    __half2 h0 = __float22half2_rn(make_float2(av0.x, av0.y));
                    __half2 h1 = __float22half2_rn(make_float2(av0.z, av0.w));
                    __half2 h2 = __float22half2_rn(make_float2(av1.x, av1.y));
                    __half2 h3 = __float22half2_rn(make_float2(av1.z, av1.w));
                    u = make_uint4(*(uint32_t*)&h0, *(uint32_t*)&h1,
                                   *(uint32_t*)&h2, *(uint32_t*)&h3);
                }
                *(uint4*)&sA[nxt * A_BUF_H + arow * A_PITCH + aseg] = u;
                CP_WAIT0();
            }
            __syncthreads();
        }
    }

    // ---------- epilogue ----------
    if (!multi && tid < N_TILE) {
        sBias[tid] = bias[(size_t)t_first * N_DIM + n0 + tid];
    }
    __syncthreads();

    const int lrow = lane >> 2;
    const int lcol = (lane & 3) * 2;
    #pragma unroll
    for (int mi = 0; mi < 2; ++mi) {
        #pragma unroll
        for (int rr = 0; rr < 2; ++rr) {
            const int rowg = m0 + wm * 32 + mi * 16 + rr * 8 + lrow;
            const float* brow = bias + (size_t)tv[rowg] * N_DIM + n0;  // used if multi
            float* op = out + (size_t)rowg * N_DIM + n0;
            #pragma unroll
            for (int nb = 0; nb < 8; ++nb) {
                const int c = wn * 64 + nb * 8 + lcol;   // col within N-tile
                float b0, b1;
                if (multi) { b0 = brow[c]; b1 = brow[c + 1]; }
                else       { b0 = sBias[c]; b1 = sBias[c + 1]; }
                float2 o;
                o.x = acc[mi][nb][rr * 2 + 0] + b0;
                o.y = acc[mi][nb][rr * 2 + 1] + b1;
                *(float2*)(op + c) = o;
            }
        }
    }
}

// ===================== launch =====================
// Inputs bound BY ELEMENT COUNT (pairwise distinct):
//   x: 67108864 f32, weight: 2097152 f32, type_vec: 131072 int32, bias: 4096 f32
extern "C" void kernel_launch(void* const* d_in, const int* in_sizes, int n_in,
                              void* d_out, int out_size) {
    const float* x    = nullptr;
    const int*   tv   = nullptr;
    const float* w    = nullptr;
    const float* bias = nullptr;

    int x_elems = 0;
    for (int i = 0; i < n_in; ++i) {
        const int sz = in_sizes[i];
        if (sz == N_TYPES * K_DIM * N_DIM) {
            w = (const float*)d_in[i];
        } else if (sz == N_TYPES * N_DIM) {
            bias = (const float*)d_in[i];
        } else if (sz >= 2 * N_TYPES * K_DIM * N_DIM) {
            x = (const float*)d_in[i];
            x_elems = sz;
        } else {
            tv = (const int*)d_in[i];
        }
    }

    const int nrows = x_elems / K_DIM;                        // 131072
    const int grid  = (nrows / M_TILE) * (N_DIM / N_TILE);    // 2048

    cudaFuncSetAttribute(hetero_gemm_kernel,
                         cudaFuncAttributeMaxDynamicSharedMemorySize, SMEM_TOTAL);

    hetero_prep_kernel<<<(N_TYPES * K_DIM * N_DIM) / (256 * 4), 256>>>(w);
    hetero_gemm_kernel<<<grid, THREADS, SMEM_TOTAL>>>(x, tv, bias, (float*)d_out);
}

// round 17
// speedup vs baseline: 1.2473x; 1.0004x over previous
#include <cuda_runtime.h>
#include <cuda_fp16.h>
#include <cstdint>

// ===================== problem constants =====================
#define N_TYPES   8
#define K_DIM     512
#define N_DIM     512
#define M_TILE    128
#define N_TILE    256
#define K_CHUNK   32
#define N_CHUNKS  (K_DIM / K_CHUNK)   // 16
#define THREADS   512

// A smem: 128 rows x 32 halves, pitch 40 halves (80B) -> conflict-free ldmatrix
#define A_PITCH   40
#define A_BUF_H   (M_TILE * A_PITCH)          // 5120 halves / stage
// B smem: 32 rows x 256 halves, pitch 264 halves (528B)
#define B_PITCH   264
#define B_BUF_H   (K_CHUNK * B_PITCH)         // 8448 halves / stage

#define SMEM_A_BYTES (2 * A_BUF_H * 2)        // 20480
#define SMEM_B_BYTES (2 * B_BUF_H * 2)        // 33792
#define SMEM_TOTAL   (SMEM_A_BYTES + SMEM_B_BYTES + N_TILE * 4)  // 55296

// fp16 weight image: [type][k][n], same linear layout as input weight
__device__ __half g_Wh[N_TYPES * K_DIM * N_DIM];   // 4 MB

// ===================== PTX helpers =====================
static __device__ __forceinline__ uint32_t smem_u32(const void* p) {
    return (uint32_t)__cvta_generic_to_shared(p);
}

static __device__ __forceinline__ void ldsm_x4(uint32_t r[4], uint32_t addr) {
    asm volatile("ldmatrix.sync.aligned.m8n8.x4.shared.b16 {%0,%1,%2,%3}, [%4];"
                 : "=r"(r[0]), "=r"(r[1]), "=r"(r[2]), "=r"(r[3]) : "r"(addr) : "memory");
}

static __device__ __forceinline__ void ldsm_x4_t(uint32_t r[4], uint32_t addr) {
    asm volatile("ldmatrix.sync.aligned.m8n8.x4.trans.shared.b16 {%0,%1,%2,%3}, [%4];"
                 : "=r"(r[0]), "=r"(r[1]), "=r"(r[2]), "=r"(r[3]) : "r"(addr) : "memory");
}

static __device__ __forceinline__ void mma_16816(float c[4], const uint32_t a[4],
                                                 uint32_t b0, uint32_t b1) {
    asm volatile(
        "mma.sync.aligned.m16n8k16.row.col.f32.f16.f16.f32 "
        "{%0,%1,%2,%3}, {%4,%5,%6,%7}, {%8,%9}, {%0,%1,%2,%3};"
        : "+f"(c[0]), "+f"(c[1]), "+f"(c[2]), "+f"(c[3])
        : "r"(a[0]), "r"(a[1]), "r"(a[2]), "r"(a[3]), "r"(b0), "r"(b1));
}

static __device__ __forceinline__ void cp_async16(uint32_t dst, const void* src) {
    asm volatile("cp.async.cg.shared.global [%0], [%1], 16;"
                 :: "r"(dst), "l"(src) : "memory");
}

#define CP_COMMIT() asm volatile("cp.async.commit_group;" ::: "memory")
#define CP_WAIT0()  asm volatile("cp.async.wait_group 0;"  ::: "memory")

// ===================== prepass: weight f32 -> f16 image =====================
__global__ void hetero_prep_kernel(const float* __restrict__ w) {
    int i = (blockIdx.x * blockDim.x + threadIdx.x) * 4;   // exact grid
    float4 v = *(const float4*)(w + i);
    __half2 h0 = __float22half2_rn(make_float2(v.x, v.y));
    __half2 h1 = __float22half2_rn(make_float2(v.z, v.w));
    uint2 u;
    u.x = *(uint32_t*)&h0;
    u.y = *(uint32_t*)&h1;
    *(uint2*)&g_Wh[i] = u;
}

// ===================== main GEMM kernel =====================
__global__ void __launch_bounds__(THREADS, 1)
hetero_gemm_kernel(const float* __restrict__ x,
                   const int* __restrict__ tv,
                   const float* __restrict__ bias,
                   float* __restrict__ out) {
    extern __shared__ __align__(16) char smem[];
    __half* sA    = (__half*)smem;                              // 2 stages
    __half* sB    = (__half*)(smem + SMEM_A_BYTES);             // 2 stages
    float*  sBias = (float*)(smem + SMEM_A_BYTES + SMEM_B_BYTES);

    const int tid  = threadIdx.x;
    const int lane = tid & 31;
    const int warp = tid >> 5;
    const int wm   = warp >> 2;         // 0..3  (M, 32 rows each)
    const int wn   = warp & 3;          // 0..3  (N, 64 cols each)

    const int bx = blockIdx.x;
    const int m0 = (bx >> 1) * M_TILE;
    const int n0 = (bx & 1)  * N_TILE;

    const int t_first = tv[m0];
    const int t_last  = tv[m0 + M_TILE - 1];
    const bool multi  = (t_first != t_last);

    // ---- A staging geometry: 4 threads/row, 8 floats each ----
    const int arow = tid >> 2;                    // 0..127
    const int aseg = (tid & 3) * 8;               // k offset within 32-chunk
    const int rt_row = tv[m0 + arow];

    // ---- B staging geometry: 16 threads/row, 16 halves (2 x uint4) each ----
    const int b_row = tid >> 4;                   // 0..31
    const int b_col = (tid & 15) * 16;            // halves within 256-col row

    const uint32_t sAu = smem_u32(sA);
    const uint32_t sBu = smem_u32(sB);

    const int l16 = lane & 15;
    const int lh8 = (lane >> 4) * 8;

    float acc[2][8][4];                 // [mi 16-row][nb 8-col][frag]
    #pragma unroll
    for (int i = 0; i < 2; ++i)
        #pragma unroll
        for (int j = 0; j < 8; ++j)
            #pragma unroll
            for (int q = 0; q < 4; ++q) acc[i][j][q] = 0.f;

    for (int t = t_first; t <= t_last; ++t) {
        const __half* wsrc = g_Wh + (size_t)t * (K_DIM * N_DIM);
        const bool amask = !multi || (rt_row == t);
        const float* xrow = x + (size_t)(m0 + arow) * K_DIM + aseg;

        float4 av0, av1;

        // ---------- prologue: stage chunk 0 into stage 0 ----------
        {
            const __half* bsrc = wsrc + (size_t)b_row * N_DIM + n0 + b_col;
            uint32_t bdst = sBu + (uint32_t)(b_row * B_PITCH + b_col) * 2u;
            cp_async16(bdst,      bsrc);
            cp_async16(bdst + 16, bsrc + 8);
            CP_COMMIT();
            uint4 u = make_uint4(0, 0, 0, 0);
            if (amask) {
                av0 = *(const float4*)(xrow);
                av1 = *(const float4*)(xrow + 4);
                __half2 h0 = __float22half2_rn(make_float2(av0.x, av0.y));
                __half2 h1 = __float22half2_rn(make_float2(av0.z, av0.w));
                __half2 h2 = __float22half2_rn(make_float2(av1.x, av1.y));
                __half2 h3 = __float22half2_rn(make_float2(av1.z, av1.w));
                u = make_uint4(*(uint32_t*)&h0, *(uint32_t*)&h1,
                               *(uint32_t*)&h2, *(uint32_t*)&h3);
            }
            *(uint4*)&sA[arow * A_PITCH + aseg] = u;
            CP_WAIT0();
            __syncthreads();
        }

        // ---------- main loop over K chunks ----------
        for (int kc = 0; kc < N_CHUNKS; ++kc) {
            const int cur = kc & 1;
            const int nxt = cur ^ 1;
            const bool not_last = (kc + 1 < N_CHUNKS) || (t < t_last);

            if (kc + 1 < N_CHUNKS) {
                // stage B(kc+1) via cp.async into nxt
                const __half* bsrc = wsrc + (size_t)((kc + 1) * K_CHUNK + b_row) * N_DIM
                                   + n0 + b_col;
                uint32_t bdst = sBu + (uint32_t)(nxt * B_BUF_H + b_row * B_PITCH + b_col) * 2u;
                cp_async16(bdst,      bsrc);
                cp_async16(bdst + 16, bsrc + 8);
                CP_COMMIT();
                // prefetch A(kc+1) into regs
                if (amask) {
                    av0 = *(const float4*)(xrow + (kc + 1) * K_CHUNK);
                    av1 = *(const float4*)(xrow + (kc + 1) * K_CHUNK + 4);
                }
            }

            // ---- MMA on cur stage: 2 x k16 steps ----
            const uint32_t abase = sAu + (uint32_t)(cur * A_BUF_H) * 2u;
            const uint32_t bbase = sBu + (uint32_t)(cur * B_BUF_H) * 2u;
            #pragma unroll
            for (int ks = 0; ks < 2; ++ks) {
                uint32_t a0[4], a1[4];
                uint32_t aaddr = abase
                    + (uint32_t)((wm * 32 + l16) * A_PITCH + ks * 16 + lh8) * 2u;
                ldsm_x4(a0, aaddr);
                ldsm_x4(a1, aaddr + (uint32_t)(16 * A_PITCH) * 2u);
                #pragma unroll
                for (int nb4 = 0; nb4 < 4; ++nb4) {
                    uint32_t b[4];
                    uint32_t baddr = bbase
                        + (uint32_t)((ks * 16 + l16) * B_PITCH + wn * 64 + nb4 * 16 + lh8) * 2u;
                    ldsm_x4_t(b, baddr);
                    mma_16816(acc[0][2 * nb4],     a0, b[0], b[1]);
                    mma_16816(acc[0][2 * nb4 + 1], a0, b[2], b[3]);
                    mma_16816(acc[1][2 * nb4],     a1, b[0], b[1]);
                    mma_16816(acc[1][2 * nb4 + 1], a1, b[2], b[3]);
                }
            }

            if (kc + 1 < N_CHUNKS) {
                // convert + STS A(kc+1) into nxt
                uint4 u = make_uint4(0, 0, 0, 0);
                if (amask) {
                    __half2 h0 = __float22half2_rn(make_float2(av0.x, av0.y));
                    __half2 h1 = __float22half2_rn(make_float2(av0.z, av0.w));
                    __half2 h2 = __float22half2_rn(make_float2(av1.x, av1.y));
                    __half2 h3 = __float22half2_rn(make_float2(av1.z, av1.w));
                    u = make_uint4(*(uint32_t*)&h0, *(uint32_t*)&h1,
                                   *(uint32_t*)&h2, *(uint32_t*)&h3);
                }
                *(uint4*)&sA[nxt * A_BUF_H + arow * A_PITCH + aseg] = u;
                CP_WAIT0();
            }
            if (not_last) __syncthreads();   // last chunk of last type: epilogue syncs
        }
    }

    // ---------- epilogue ----------
    if (!multi && tid < N_TILE) {
        sBias[tid] = bias[(size_t)t_first * N_DIM + n0 + tid];
    }
    __syncthreads();

    const int lrow = lane >> 2;
    const int lcol = (lane & 3) * 2;
    #pragma unroll
    for (int mi = 0; mi < 2; ++mi) {
        #pragma unroll
        for (int rr = 0; rr < 2; ++rr) {
            const int rowg = m0 + wm * 32 + mi * 16 + rr * 8 + lrow;
            const float* brow = bias + (size_t)tv[rowg] * N_DIM + n0;  // used if multi
            float* op = out + (size_t)rowg * N_DIM + n0;
            #pragma unroll
            for (int nb = 0; nb < 8; ++nb) {
                const int c = wn * 64 + nb * 8 + lcol;   // col within N-tile
                float b0, b1;
                if (multi) { b0 = brow[c]; b1 = brow[c + 1]; }
                else       { b0 = sBias[c]; b1 = sBias[c + 1]; }
                float2 o;
                o.x = acc[mi][nb][rr * 2 + 0] + b0;
                o.y = acc[mi][nb][rr * 2 + 1] + b1;
                *(float2*)(op + c) = o;
            }
        }
    }
}

// ===================== launch =====================
// Inputs bound BY ELEMENT COUNT (pairwise distinct):
//   x: 67108864 f32, weight: 2097152 f32, type_vec: 131072 int32, bias: 4096 f32
extern "C" void kernel_launch(void* const* d_in, const int* in_sizes, int n_in,
                              void* d_out, int out_size) {
    const float* x    = nullptr;
    const int*   tv   = nullptr;
    const float* w    = nullptr;
    const float* bias = nullptr;

    int x_elems = 0;
    for (int i = 0; i < n_in; ++i) {
        const int sz = in_sizes[i];
        if (sz == N_TYPES * K_DIM * N_DIM) {
            w = (const float*)d_in[i];
        } else if (sz == N_TYPES * N_DIM) {
            bias = (const float*)d_in[i];
        } else if (sz >= 2 * N_TYPES * K_DIM * N_DIM) {
            x = (const float*)d_in[i];
            x_elems = sz;
        } else {
            tv = (const int*)d_in[i];
        }
    }

    const int nrows = x_elems / K_DIM;                        // 131072
    const int grid  = (nrows / M_TILE) * (N_DIM / N_TILE);    // 2048

    cudaFuncSetAttribute(hetero_gemm_kernel,
                         cudaFuncAttributeMaxDynamicSharedMemorySize, SMEM_TOTAL);

    hetero_prep_kernel<<<(N_TYPES * K_DIM * N_DIM) / (256 * 4), 256>>>(w);
    hetero_gemm_kernel<<<grid, THREADS, SMEM_TOTAL>>>(x, tv, bias, (float*)d_out);
}